// round 1
// baseline (speedup 1.0000x reference)
#include <cuda_runtime.h>
#include <math_constants.h>

// CollectNeighbourAverageAndMax: V=100000, K=32, F=64
// out[v, 0:64]   = sum_k x[idxs[v,k], :] / 32
// out[v, 64:128] = max_k x[idxs[v,k], :]
//
// One warp per vertex. K == 32 == warpSize:
//   - lane loads its own neighbor index (coalesced)
//   - shfl broadcasts index k to all lanes
//   - each lane owns features [2*lane, 2*lane+1] as a float2
// Fully unrolled K loop -> 32 independent LDG.64 in flight (L2-resident x).

__global__ void __launch_bounds__(256)
collect_nbr_avg_max_kernel(const float* __restrict__ x,
                           const int* __restrict__ idxs,
                           float* __restrict__ out,
                           int V) {
    const int warp_id = (blockIdx.x * blockDim.x + threadIdx.x) >> 5;
    const int lane = threadIdx.x & 31;
    if (warp_id >= V) return;

    const int v = warp_id;

    // Coalesced load of all 32 neighbor indices for this vertex (one per lane).
    const int my_idx = idxs[(size_t)v * 32 + lane];

    float2 s = make_float2(0.0f, 0.0f);
    float2 m = make_float2(-CUDART_INF_F, -CUDART_INF_F);

#pragma unroll
    for (int k = 0; k < 32; ++k) {
        const int nbr = __shfl_sync(0xffffffffu, my_idx, k);
        // Row of x: 64 floats = 32 float2; lane grabs its float2.
        const float2 val =
            reinterpret_cast<const float2*>(x + (size_t)nbr * 64)[lane];
        s.x += val.x;
        s.y += val.y;
        m.x = fmaxf(m.x, val.x);
        m.y = fmaxf(m.y, val.y);
    }

    float2* o = reinterpret_cast<float2*>(out + (size_t)v * 128);
    o[lane] = make_float2(s.x * (1.0f / 32.0f), s.y * (1.0f / 32.0f));
    o[32 + lane] = m;
}

extern "C" void kernel_launch(void* const* d_in, const int* in_sizes, int n_in,
                              void* d_out, int out_size) {
    const float* x = (const float*)d_in[0];     // [V, 64] f32
    const int* idxs = (const int*)d_in[1];      // [V, 32] i32
    float* out = (float*)d_out;                 // [V, 128] f32

    const int V = in_sizes[1] / 32;

    const int threads = 256;                    // 8 warps -> 8 vertices/block
    const int warps_per_block = threads / 32;
    const int blocks = (V + warps_per_block - 1) / warps_per_block;

    collect_nbr_avg_max_kernel<<<blocks, threads>>>(x, idxs, out, V);
}

// round 2
// speedup vs baseline: 1.2655x; 1.2655x over previous
#include <cuda_runtime.h>
#include <cuda_fp16.h>
#include <math_constants.h>

// CollectNeighbourAverageAndMax: V=100000, K=32, F=64
// Round 2: the kernel is at the LTS (L2 data-path) chip ceiling (~6600 B/cyc).
// Only lever: halve gather bytes. Pre-convert x f32 -> f16 (device-global
// scratch, 12.8 MB), then gather 128B rows (one cache line per neighbor).
// fp32 accumulation; expected rel_err ~3e-4 << 1e-3 tolerance.

#define V_MAX 100000
#define F_DIM 64

__device__ __half g_xh[(size_t)V_MAX * F_DIM];  // 12.8 MB scratch

// ---- Kernel A: convert x [V,64] f32 -> f16 --------------------------------
__global__ void __launch_bounds__(256)
convert_x_kernel(const float* __restrict__ x, int n4) {
    const int i = blockIdx.x * blockDim.x + threadIdx.x;
    if (i >= n4) return;
    const float4 v = reinterpret_cast<const float4*>(x)[i];
    const __half2 h0 = __floats2half2_rn(v.x, v.y);
    const __half2 h1 = __floats2half2_rn(v.z, v.w);
    uint2 packed;
    packed.x = *reinterpret_cast<const unsigned int*>(&h0);
    packed.y = *reinterpret_cast<const unsigned int*>(&h1);
    reinterpret_cast<uint2*>(g_xh)[i] = packed;
}

// ---- Kernel B: warp-per-vertex gather + mean/max --------------------------
// Lane loads its own neighbor index (coalesced); shfl broadcasts index k.
// Row of x in fp16 = 64 halves = 128 B = ONE cache line: lane grabs half2.
__global__ void __launch_bounds__(256)
collect_nbr_avg_max_f16(const int* __restrict__ idxs,
                        float* __restrict__ out,
                        int V) {
    const int warp_id = (blockIdx.x * blockDim.x + threadIdx.x) >> 5;
    const int lane = threadIdx.x & 31;
    if (warp_id >= V) return;

    const int my_idx = idxs[(size_t)warp_id * 32 + lane];

    float2 s = make_float2(0.0f, 0.0f);
    float2 m = make_float2(-CUDART_INF_F, -CUDART_INF_F);

    const __half2* __restrict__ xh = reinterpret_cast<const __half2*>(g_xh);

#pragma unroll
    for (int k = 0; k < 32; ++k) {
        const int nbr = __shfl_sync(0xffffffffu, my_idx, k);
        // Row nbr: 32 half2's; lane grabs its half2 (4 B) -> warp covers 128 B.
        const __half2 h = xh[(size_t)nbr * 32 + lane];
        const float2 v = __half22float2(h);
        s.x += v.x;
        s.y += v.y;
        m.x = fmaxf(m.x, v.x);
        m.y = fmaxf(m.y, v.y);
    }

    float2* o = reinterpret_cast<float2*>(out + (size_t)warp_id * 128);
    o[lane] = make_float2(s.x * (1.0f / 32.0f), s.y * (1.0f / 32.0f));
    o[32 + lane] = m;
}

extern "C" void kernel_launch(void* const* d_in, const int* in_sizes, int n_in,
                              void* d_out, int out_size) {
    const float* x = (const float*)d_in[0];   // [V, 64] f32
    const int* idxs = (const int*)d_in[1];    // [V, 32] i32
    float* out = (float*)d_out;               // [V, 128] f32

    const int V = in_sizes[1] / 32;

    // Kernel A: convert V*64 floats, 4 per thread.
    const int n4 = V * (F_DIM / 4);
    convert_x_kernel<<<(n4 + 255) / 256, 256>>>(x, n4);

    // Kernel B: one warp per vertex.
    const int threads = 256;
    const int warps_per_block = threads / 32;
    const int blocks = (V + warps_per_block - 1) / warps_per_block;
    collect_nbr_avg_max_f16<<<blocks, threads>>>(idxs, out, V);
}

// round 3
// speedup vs baseline: 1.6493x; 1.3033x over previous
#include <cuda_runtime.h>
#include <cuda_fp16.h>
#include <math_constants.h>

// CollectNeighbourAverageAndMax: V=100000, K=32, F=64
// Round 3: kernel is instruction-issue-bound (issue=72.9%, L2=37.9%).
// Cut warp-instructions per neighbor:
//  - LDG.64 per lane -> warp covers 2 rows per load (half-warp per neighbor)
//  - max kept packed in half2 (HMNMX2)
//  - fp16 pairwise pre-add for the sum (HADD2), fp32 accumulation of pairs

#define V_MAX 100000
#define F_DIM 64

__device__ __half g_xh[(size_t)V_MAX * F_DIM];  // 12.8 MB scratch

// ---- Kernel A: convert x [V,64] f32 -> f16 --------------------------------
__global__ void __launch_bounds__(256)
convert_x_kernel(const float* __restrict__ x, int n4) {
    const int i = blockIdx.x * blockDim.x + threadIdx.x;
    if (i >= n4) return;
    const float4 v = reinterpret_cast<const float4*>(x)[i];
    const __half2 h0 = __floats2half2_rn(v.x, v.y);
    const __half2 h1 = __floats2half2_rn(v.z, v.w);
    uint2 packed;
    packed.x = *reinterpret_cast<const unsigned int*>(&h0);
    packed.y = *reinterpret_cast<const unsigned int*>(&h1);
    reinterpret_cast<uint2*>(g_xh)[i] = packed;
}

// ---- Kernel B: warp-per-vertex, 2 neighbors per iteration -----------------
// half = lane>>4 selects which of the 2 broadcast neighbors this lane serves;
// sub = lane&15 selects the 8-byte (4-feature) chunk of the 128B row.
__global__ void __launch_bounds__(256)
collect_nbr_avg_max_f16d(const int* __restrict__ idxs,
                         float* __restrict__ out,
                         int V) {
    const int warp_id = (blockIdx.x * blockDim.x + threadIdx.x) >> 5;
    if (warp_id >= V) return;
    const int lane = threadIdx.x & 31;
    const int half = lane >> 4;   // 0: even neighbors, 1: odd neighbors
    const int sub = lane & 15;    // feature chunk [4*sub, 4*sub+4)

    // Pre-scaled byte offset of this lane's neighbor row.
    const int my_off = idxs[(size_t)warp_id * 32 + lane] << 7;  // *128 bytes

    const char* base = reinterpret_cast<const char*>(g_xh) + sub * 8;

    float2 s0 = make_float2(0.0f, 0.0f);
    float2 s1 = make_float2(0.0f, 0.0f);
    __half2 m0 = __float2half2_rn(-CUDART_INF_F);
    __half2 m1 = __float2half2_rn(-CUDART_INF_F);

#pragma unroll
    for (int k = 0; k < 16; k += 2) {
        // Two iterations fused: neighbors (2k+half) and (2k+2+half).
        const int off0 = __shfl_sync(0xffffffffu, my_off, 2 * k + half);
        const int off1 = __shfl_sync(0xffffffffu, my_off, 2 * k + 2 + half);
        const uint2 u0 = *reinterpret_cast<const uint2*>(base + off0);
        const uint2 u1 = *reinterpret_cast<const uint2*>(base + off1);

        const __half2 a0 = *reinterpret_cast<const __half2*>(&u0.x);
        const __half2 a1 = *reinterpret_cast<const __half2*>(&u0.y);
        const __half2 b0 = *reinterpret_cast<const __half2*>(&u1.x);
        const __half2 b1 = *reinterpret_cast<const __half2*>(&u1.y);

        // Max: fully packed fp16.
        m0 = __hmax2(m0, __hmax2(a0, b0));
        m1 = __hmax2(m1, __hmax2(a1, b1));

        // Sum: one fp16 pair-add, then fp32 accumulate.
        const float2 f0 = __half22float2(__hadd2(a0, b0));
        const float2 f1 = __half22float2(__hadd2(a1, b1));
        s0.x += f0.x; s0.y += f0.y;
        s1.x += f1.x; s1.y += f1.y;
    }

    // Cross-half combine (lanes l and l^16 hold same features, disjoint k sets).
    {
        unsigned mm0 = __shfl_xor_sync(0xffffffffu,
                                       *reinterpret_cast<const unsigned*>(&m0), 16);
        unsigned mm1 = __shfl_xor_sync(0xffffffffu,
                                       *reinterpret_cast<const unsigned*>(&m1), 16);
        m0 = __hmax2(m0, *reinterpret_cast<const __half2*>(&mm0));
        m1 = __hmax2(m1, *reinterpret_cast<const __half2*>(&mm1));
    }
    s0.x += __shfl_xor_sync(0xffffffffu, s0.x, 16);
    s0.y += __shfl_xor_sync(0xffffffffu, s0.y, 16);
    s1.x += __shfl_xor_sync(0xffffffffu, s1.x, 16);
    s1.y += __shfl_xor_sync(0xffffffffu, s1.y, 16);

    // Output row: [mean(64) | max(64)]. Lanes 0-15 write mean, 16-31 write max.
    float* orow = out + (size_t)warp_id * 128;
    if (half == 0) {
        const float4 mean = make_float4(s0.x * (1.0f / 32.0f),
                                        s0.y * (1.0f / 32.0f),
                                        s1.x * (1.0f / 32.0f),
                                        s1.y * (1.0f / 32.0f));
        *reinterpret_cast<float4*>(orow + sub * 4) = mean;
    } else {
        const float2 x0 = __half22float2(m0);
        const float2 x1 = __half22float2(m1);
        *reinterpret_cast<float4*>(orow + 64 + sub * 4) =
            make_float4(x0.x, x0.y, x1.x, x1.y);
    }
}

extern "C" void kernel_launch(void* const* d_in, const int* in_sizes, int n_in,
                              void* d_out, int out_size) {
    const float* x = (const float*)d_in[0];   // [V, 64] f32
    const int* idxs = (const int*)d_in[1];    // [V, 32] i32
    float* out = (float*)d_out;               // [V, 128] f32

    const int V = in_sizes[1] / 32;

    const int n4 = V * (F_DIM / 4);
    convert_x_kernel<<<(n4 + 255) / 256, 256>>>(x, n4);

    const int threads = 256;  // 8 warps -> 8 vertices/block
    const int warps_per_block = threads / 32;
    const int blocks = (V + warps_per_block - 1) / warps_per_block;
    collect_nbr_avg_max_f16d<<<blocks, threads>>>(idxs, out, V);
}

// round 5
// speedup vs baseline: 1.7455x; 1.0583x over previous
#include <cuda_runtime.h>
#include <cuda_fp16.h>
#include <math_constants.h>

// CollectNeighbourAverageAndMax: V=100000, K=32, F=64
// Round 4: shave loop instructions toward the LTS cap.
//  - LDG.128 per lane: warp covers 4 neighbor rows per load
//  - full fp16 accumulation (sum via HADD2, max via HMNMX2); round-3 evidence
//    shows quantization dominates error, accumulation adds ~nothing
//  - epilogue: xor-shfl reduction across lane quads, one STG.128 per lane

#define V_MAX 100000
#define F_DIM 64

__device__ __half g_xh[(size_t)V_MAX * F_DIM];  // 12.8 MB scratch

// ---- Kernel A: convert x [V,64] f32 -> f16, 8 floats per thread -----------
__global__ void __launch_bounds__(256)
convert_x_kernel(const float* __restrict__ x, int n8) {
    const int i = blockIdx.x * blockDim.x + threadIdx.x;
    if (i >= n8) return;
    const float4 v0 = reinterpret_cast<const float4*>(x)[2 * i];
    const float4 v1 = reinterpret_cast<const float4*>(x)[2 * i + 1];
    const __half2 h0 = __floats2half2_rn(v0.x, v0.y);
    const __half2 h1 = __floats2half2_rn(v0.z, v0.w);
    const __half2 h2 = __floats2half2_rn(v1.x, v1.y);
    const __half2 h3 = __floats2half2_rn(v1.z, v1.w);
    uint4 p;
    p.x = *reinterpret_cast<const unsigned*>(&h0);
    p.y = *reinterpret_cast<const unsigned*>(&h1);
    p.z = *reinterpret_cast<const unsigned*>(&h2);
    p.w = *reinterpret_cast<const unsigned*>(&h3);
    reinterpret_cast<uint4*>(g_xh)[i] = p;
}

// ---- Kernel B: warp-per-vertex, 4 neighbors per LDG.128 -------------------
// quad = lane>>3 : which of the 4 broadcast neighbors this lane serves
// sub  = lane&7  : 16-byte (8-feature) chunk of the 128 B row
__global__ void __launch_bounds__(256)
collect_nbr_avg_max_q(const int* __restrict__ idxs,
                      float* __restrict__ out,
                      int V) {
    const int warp_id = (blockIdx.x * blockDim.x + threadIdx.x) >> 5;
    if (warp_id >= V) return;
    const int lane = threadIdx.x & 31;
    const int quad = lane >> 3;
    const int sub = lane & 7;
    const int q8 = lane & 24;  // quad * 8

    // Byte offset of this lane's neighbor row (rows are 128 B).
    const int my_off = idxs[(size_t)warp_id * 32 + lane] << 7;

    const char* base = reinterpret_cast<const char*>(g_xh) + (sub << 4);

    __half2 s0, s1, s2, s3;
    s0 = s1 = s2 = s3 = __float2half2_rn(0.0f);
    __half2 m0, m1, m2, m3;
    m0 = m1 = m2 = m3 = __float2half2_rn(-CUDART_INF_F);

#pragma unroll
    for (int k = 0; k < 8; ++k) {
        // Iteration k: quad q handles neighbor stored in lane q*8 + k.
        const int off = __shfl_sync(0xffffffffu, my_off, q8 + k);
        const uint4 u = *reinterpret_cast<const uint4*>(base + off);
        const __half2 a0 = *reinterpret_cast<const __half2*>(&u.x);
        const __half2 a1 = *reinterpret_cast<const __half2*>(&u.y);
        const __half2 a2 = *reinterpret_cast<const __half2*>(&u.z);
        const __half2 a3 = *reinterpret_cast<const __half2*>(&u.w);
        s0 = __hadd2(s0, a0);
        s1 = __hadd2(s1, a1);
        s2 = __hadd2(s2, a2);
        s3 = __hadd2(s3, a3);
        m0 = __hmax2(m0, a0);
        m1 = __hmax2(m1, a1);
        m2 = __hmax2(m2, a2);
        m3 = __hmax2(m3, a3);
    }

    // Reduce across the 4 quads (lane bits 3 and 4). Each quad holds a
    // disjoint set of 8 neighbors for the SAME feature chunk.
#pragma unroll
    for (int d = 8; d <= 16; d <<= 1) {
        unsigned t;
        t = __shfl_xor_sync(0xffffffffu, *reinterpret_cast<unsigned*>(&s0), d);
        s0 = __hadd2(s0, *reinterpret_cast<__half2*>(&t));
        t = __shfl_xor_sync(0xffffffffu, *reinterpret_cast<unsigned*>(&s1), d);
        s1 = __hadd2(s1, *reinterpret_cast<__half2*>(&t));
        t = __shfl_xor_sync(0xffffffffu, *reinterpret_cast<unsigned*>(&s2), d);
        s2 = __hadd2(s2, *reinterpret_cast<__half2*>(&t));
        t = __shfl_xor_sync(0xffffffffu, *reinterpret_cast<unsigned*>(&s3), d);
        s3 = __hadd2(s3, *reinterpret_cast<__half2*>(&t));
        t = __shfl_xor_sync(0xffffffffu, *reinterpret_cast<unsigned*>(&m0), d);
        m0 = __hmax2(m0, *reinterpret_cast<__half2*>(&t));
        t = __shfl_xor_sync(0xffffffffu, *reinterpret_cast<unsigned*>(&m1), d);
        m1 = __hmax2(m1, *reinterpret_cast<__half2*>(&t));
        t = __shfl_xor_sync(0xffffffffu, *reinterpret_cast<unsigned*>(&m2), d);
        m2 = __hmax2(m2, *reinterpret_cast<__half2*>(&t));
        t = __shfl_xor_sync(0xffffffffu, *reinterpret_cast<unsigned*>(&m3), d);
        m3 = __hmax2(m3, *reinterpret_cast<__half2*>(&t));
    }

    // Mean = sum * 2^-5 (exact in fp16).
    const __half2 inv32 = __float2half2_rn(0.03125f);
    s0 = __hmul2(s0, inv32);
    s1 = __hmul2(s1, inv32);
    s2 = __hmul2(s2, inv32);
    s3 = __hmul2(s3, inv32);

    // Each lane writes one float4 of the 128-float output row:
    //   quad0: mean[8sub .. 8sub+4)      quad1: mean[8sub+4 .. 8sub+8)
    //   quad2: max [8sub .. 8sub+4)      quad3: max [8sub+4 .. 8sub+8)
    __half2 lo, hi;
    float* orow = out + (size_t)warp_id * 128;
    float* ptr;
    if (quad == 0)      { lo = s0; hi = s1; ptr = orow + 8 * sub; }
    else if (quad == 1) { lo = s2; hi = s3; ptr = orow + 8 * sub + 4; }
    else if (quad == 2) { lo = m0; hi = m1; ptr = orow + 64 + 8 * sub; }
    else                { lo = m2; hi = m3; ptr = orow + 64 + 8 * sub + 4; }

    const float2 fa = __half22float2(lo);
    const float2 fb = __half22float2(hi);
    *reinterpret_cast<float4*>(ptr) = make_float4(fa.x, fa.y, fb.x, fb.y);
}

extern "C" void kernel_launch(void* const* d_in, const int* in_sizes, int n_in,
                              void* d_out, int out_size) {
    const float* x = (const float*)d_in[0];   // [V, 64] f32
    const int* idxs = (const int*)d_in[1];    // [V, 32] i32
    float* out = (float*)d_out;               // [V, 128] f32

    const int V = in_sizes[1] / 32;

    const int n8 = V * (F_DIM / 8);
    convert_x_kernel<<<(n8 + 255) / 256, 256>>>(x, n8);

    const int threads = 256;  // 8 warps -> 8 vertices/block
    const int warps_per_block = threads / 32;
    const int blocks = (V + warps_per_block - 1) / warps_per_block;
    collect_nbr_avg_max_q<<<blocks, threads>>>(idxs, out, V);
}